// round 6
// baseline (speedup 1.0000x reference)
#include <cuda_runtime.h>
#include <cuda_bf16.h>
#include <cstdint>

// Problem constants: T=32768, E=256, K=8, D=8, r=2
#define E_EXPERTS 256
#define D_DEVS    8
#define K_TOPK    8
#define E_PER_DEV (E_EXPERTS / D_DEVS)   // 32
#define TOK_PER_BLK 32                   // 8 warps x 4 tokens

// Fused kernel, one launch:
//  - block-local invperm (ballot rank)
//  - zero-fill own 32-token slice of all 8 device planes via TMA bulk stores
//    (async proxy; no LSU issue cost)
//  - gather 1 selection/lane, scatter into own (zeroed) slice after bulk wait
//  - coalesced mask rows
__global__ __launch_bounds__(256) void moe_remap_tma(
    const float* __restrict__ topk,     // [T, E]
    const int*   __restrict__ mapping,  // [E, D] one-hot
    const int*   __restrict__ meta,     // [T, K]
    float*       __restrict__ out,      // [D, T, 32]
    float*       __restrict__ mask,     // [T/2, D]
    int T)
{
    __shared__ __align__(128) float zbuf[TOK_PER_BLK * E_PER_DEV];  // 4KB zeros
    __shared__ int wcnt[8][8];
    __shared__ int invperm_s[E_EXPERTS];

    const int tid  = threadIdx.x;
    const int lane = tid & 31;
    const int warp = tid >> 5;
    const int blkT = blockIdx.x * TOK_PER_BLK;       // first token of block
    const int t0   = blkT + warp * 4;                // first token of warp

    // ---- meta load first (32 contiguous ints per warp) ----
    const int e = meta[t0 * K_TOPK + lane];          // lane's selection

    // ---- invperm phase: expert->device, ballot counts ----
    {
        const int4* m4 = reinterpret_cast<const int4*>(mapping);
        const int4 a4 = m4[tid * 2];
        const int4 b4 = m4[tid * 2 + 1];
        int v[8] = {a4.x, a4.y, a4.z, a4.w, b4.x, b4.y, b4.z, b4.w};
        int best = v[0], d = 0;
#pragma unroll
        for (int i = 1; i < D_DEVS; i++)
            if (v[i] > best) { best = v[i]; d = i; }   // first max wins

        const unsigned lt = (1u << lane) - 1u;
        int within = 0, mycnt = 0;
#pragma unroll
        for (int d2 = 0; d2 < D_DEVS; d2++) {
            unsigned b = __ballot_sync(0xffffffffu, d == d2);
            if (d2 == d)    within = __popc(b & lt);
            if (lane == d2) mycnt  = __popc(b);
        }
        if (lane < D_DEVS) wcnt[warp][lane] = mycnt;

        // zero the smem staging buffer (1024 floats, 1 float4/thread)
        reinterpret_cast<float4*>(zbuf)[tid] = make_float4(0.f, 0.f, 0.f, 0.f);

        // make generic-proxy smem writes visible to the async proxy (TMA reads)
        asm volatile("fence.proxy.async.shared::cta;" ::: "memory");

        __syncthreads();   // wcnt + zbuf + fences complete block-wide

        int off = 0;
#pragma unroll
        for (int w2 = 0; w2 < 8; w2++)
#pragma unroll
            for (int d2 = 0; d2 < D_DEVS; d2++) {
                int c = wcnt[w2][d2];
                off += ((d2 < d) || (d2 == d && w2 < warp)) ? c : 0;
            }
        invperm_s[tid] = off + within;
    }

    // ---- TMA bulk zero-fill: 8 planes x 4KB, issued by thread 0 ----
    uint32_t zbuf_addr;
    asm("{ .reg .u64 t; cvta.to.shared.u64 t, %1; cvt.u32.u64 %0, t; }"
        : "=r"(zbuf_addr) : "l"(zbuf));
    if (tid == 0) {
#pragma unroll
        for (int dd = 0; dd < D_DEVS; dd++) {
            float* gdst = out + dd * (T * E_PER_DEV) + blkT * E_PER_DEV;
            asm volatile(
                "cp.async.bulk.global.shared::cta.bulk_group [%0], [%1], %2;"
                :: "l"(gdst), "r"(zbuf_addr), "r"(TOK_PER_BLK * E_PER_DEV * 4)
                : "memory");
        }
        asm volatile("cp.async.bulk.commit_group;" ::: "memory");
    }

    __syncthreads();       // invperm_s ready

    // ---- gather (overlaps with in-flight bulk stores) ----
    const int tl = lane >> 3;                               // local token 0..3
    const float v = topk[(t0 + tl) * E_EXPERTS + e];
    const int p  = invperm_s[e];
    const int d  = p >> 5, j = p & 31;

    // ---- wait for this block's zero-fill, then order scatter after it ----
    if (tid == 0)
        asm volatile("cp.async.bulk.wait_group 0;" ::: "memory");
    __syncthreads();

    // ---- scatter (duplicates write identical values: benign) ----
    out[d * (T * E_PER_DEV) + (t0 + tl) * E_PER_DEV + j] = v;

    // ---- masks: 2 pair rows per warp ----
    unsigned mc = 1u << d;
#pragma unroll
    for (int o = 8; o; o >>= 1)
        mc |= __shfl_xor_sync(0xffffffffu, mc, o);   // OR within 16-lane halves
    const unsigned other = __shfl_xor_sync(0xffffffffu, mc, 16);

    if (lane < 16) {
        const unsigned bits = (lane < 8) ? mc : other;   // pairA | pairB
        // block pairs: blk*16 .. +15 ; warp w covers pairs 2w, 2w+1
        mask[blockIdx.x * (TOK_PER_BLK / 2) * D_DEVS + warp * 16 + lane] =
            ((bits >> (lane & 7)) & 1u) ? 1.0f : 0.0f;
    }
}

extern "C" void kernel_launch(void* const* d_in, const int* in_sizes, int n_in,
                              void* d_out, int out_size) {
    const float* topk    = (const float*)d_in[0];   // [1,1,T,E]
    const int*   mapping = (const int*)  d_in[1];   // [1,1,E,D]
    const int*   meta    = (const int*)  d_in[2];   // [1,1,T,K]

    const int T = in_sizes[0] / E_EXPERTS;          // 32768

    float* out  = (float*)d_out;                            // [D, T, 32]
    float* mask = out + (size_t)D_DEVS * T * E_PER_DEV;     // [T/2, D]

    const int blocks = T / TOK_PER_BLK;             // 1024
    moe_remap_tma<<<blocks, 256>>>(topk, mapping, meta, out, mask, T);
}